// round 8
// baseline (speedup 1.0000x reference)
#include <cuda_runtime.h>
#include <cuda_bf16.h>
#include <math.h>

#define NBINS 32
#define TILE  128
#define NT    256
#define GBLK  296          // 148 SMs * 2 resident blocks
#define RQ    9            // smem row stride in float4 (8 data quads + 1 pad)
#define NCELL (NBINS * NBINS)

typedef unsigned long long ull;

// ---------------- scratch (no allocations allowed) ----------------
__device__ unsigned g_minbits;
__device__ unsigned g_maxbits;
__device__ float    g_part[NCELL * GBLK];   // [cell][block] fp32 partials (~1.2 MB)
__device__ double   g_pab[NCELL];           // fp64 joint histogram sums

// order-preserving encoding so uint atomicMin/Max give exact float min/max
__device__ __forceinline__ unsigned enc_f(float v) {
    unsigned u = __float_as_uint(v);
    return (u & 0x80000000u) ? ~u : (u | 0x80000000u);
}
__device__ __forceinline__ float dec_f(unsigned u) {
    return (u & 0x80000000u) ? __uint_as_float(u & 0x7FFFFFFFu)
                             : __uint_as_float(~u);
}

// packed fp32x2 FMA: each half is an exact IEEE fp32 FMA
__device__ __forceinline__ void ffma2(ull& d, ull a, ull b) {
    asm("fma.rn.f32x2 %0, %1, %2, %0;" : "+l"(d) : "l"(a), "l"(b));
}
__device__ __forceinline__ ull dup_f32(float v) {
    ull r;
    asm("mov.b64 %0, {%1, %1};" : "=l"(r) : "r"(__float_as_uint(v)));
    return r;
}

__global__ void mi_init() {
    g_minbits = 0xFFFFFFFFu;
    g_maxbits = 0u;
}

__global__ void mi_minmax(const float* __restrict__ p,
                          const float* __restrict__ t, int N) {
    unsigned lmin = 0xFFFFFFFFu, lmax = 0u;
    int stride = gridDim.x * blockDim.x;
    int gtid = blockIdx.x * blockDim.x + threadIdx.x;
    int n4 = N >> 2;
    const float4* p4 = (const float4*)p;
    const float4* t4 = (const float4*)t;
    for (int i = gtid; i < n4; i += stride) {
        float4 a = __ldg(p4 + i);
        float4 b = __ldg(t4 + i);
        unsigned u;
        u = enc_f(a.x); lmin = min(lmin, u); lmax = max(lmax, u);
        u = enc_f(a.y); lmin = min(lmin, u); lmax = max(lmax, u);
        u = enc_f(a.z); lmin = min(lmin, u); lmax = max(lmax, u);
        u = enc_f(a.w); lmin = min(lmin, u); lmax = max(lmax, u);
        u = enc_f(b.x); lmin = min(lmin, u); lmax = max(lmax, u);
        u = enc_f(b.y); lmin = min(lmin, u); lmax = max(lmax, u);
        u = enc_f(b.z); lmin = min(lmin, u); lmax = max(lmax, u);
        u = enc_f(b.w); lmin = min(lmin, u); lmax = max(lmax, u);
    }
    for (int i = (n4 << 2) + gtid; i < N; i += stride) {   // tail
        unsigned u = enc_f(__ldg(p + i));
        lmin = min(lmin, u); lmax = max(lmax, u);
        u = enc_f(__ldg(t + i));
        lmin = min(lmin, u); lmax = max(lmax, u);
    }
#pragma unroll
    for (int o = 16; o > 0; o >>= 1) {
        lmin = min(lmin, __shfl_xor_sync(0xFFFFFFFFu, lmin, o));
        lmax = max(lmax, __shfl_xor_sync(0xFFFFFFFFu, lmax, o));
    }
    __shared__ unsigned smin[8], smax[8];
    int wid = threadIdx.x >> 5;
    if ((threadIdx.x & 31) == 0) { smin[wid] = lmin; smax[wid] = lmax; }
    __syncthreads();
    if (threadIdx.x == 0) {
        unsigned m = smin[0], M = smax[0];
        int nw = blockDim.x >> 5;
        for (int w = 1; w < nw; w++) { m = min(m, smin[w]); M = max(M, smax[w]); }
        atomicMin(&g_minbits, m);   // exact, order-independent -> deterministic
        atomicMax(&g_maxbits, M);
    }
}

// Main kernel (smem-instruction optimized):
//   A rows stored RAW; B rows stored pre-scaled by rsa*rsb, so the FMA phase
//   needs no normalization. 8x8 register tiles with element pairing: lanes
//   0-15 / 16-31 process paired elements; 2 LDS.128 per element side.
__global__ __launch_bounds__(NT, 2)
void mi_main(const float* __restrict__ pred, const float* __restrict__ tgt,
             int N, int numTiles) {
    __shared__ float4 SH[2 * TILE * RQ];   // 36,864 B: WA then WB
    __shared__ float  rsa_s[TILE];
    float4* WA = SH;
    float4* WB = SH + TILE * RQ;

    float minv = dec_f(g_minbits);
    float maxv = dec_f(g_maxbits);
    if (maxv <= 1.0f && minv >= 0.0f) { minv = 0.0f; maxv = 1.0f; }
    float range  = maxv - minv;
    const float inv31 = 1.0f / 31.0f;
    float sigma  = range / 31.0f;                 // /(NUM_BINS-1) * SIGMA_RATIO(=1)
    float preterm = 1.0f / ((2.0f * sigma) * sigma);
    float npre   = 0.0f - preterm;

    int t    = threadIdx.x;
    int tn   = t & (TILE - 1);
    int warp = t >> 5;            // warps 0-3: A (pred), warps 4-7: B (tgt)
    bool isA = (warp < 4);
    const float* src = isA ? pred : tgt;
    float4* Wrow = (isA ? WA : WB) + tn * RQ;

    // FMA-phase roles: warp owns elements [warp*16, warp*16+16), processed as
    // 8 pairs; half = which element of the pair this lane covers.
    int lane = t & 31;
    int half = lane >> 4;         // 0 or 1
    int p16  = lane & 15;
    int kp   = p16 >> 2;          // k-block: rows 8*kp .. 8*kp+7
    int lp   = p16 & 3;           // l-block: cols 8*lp .. 8*lp+7
    const float4* Abase = WA + (warp * 16 + half) * RQ + 2 * kp;
    const float4* Bbase = WB + (warp * 16 + half) * RQ + 2 * lp;

    // packed accumulators: acc2[r][c] = cells k = 8*kp + 2r + {0,1}, l = 8*lp + c
    ull acc2[4][8];
#pragma unroll
    for (int r = 0; r < 4; r++)
#pragma unroll
        for (int c = 0; c < 8; c++) acc2[r][c] = 0ull;

    for (int tile = blockIdx.x; tile < numTiles; tile += gridDim.x) {
        __syncthreads();                      // previous tile's FMA reads complete
        int idx = tile * TILE + tn;
        float x = (idx < N) ? __ldg(src + idx) : 0.0f;

        float S = 0.0f;
        if (isA) {
            // A: compute exps once, store RAW, accumulate S (same k order)
#pragma unroll
            for (int q = 0; q < 8; q++) {
                float4 v;
                float c, d;
                c = minv + range * ((float)(4 * q + 0) * inv31); d = x - c; v.x = __expf(npre * d * d);
                c = minv + range * ((float)(4 * q + 1) * inv31); d = x - c; v.y = __expf(npre * d * d);
                c = minv + range * ((float)(4 * q + 2) * inv31); d = x - c; v.z = __expf(npre * d * d);
                c = minv + range * ((float)(4 * q + 3) * inv31); d = x - c; v.w = __expf(npre * d * d);
                S += v.x; S += v.y; S += v.z; S += v.w;
                Wrow[q] = v;
            }
            rsa_s[tn] = (idx < N) ? (1.0f / S) : 0.0f;
        } else {
            // B pass 1: normalization sum only (no stores)
#pragma unroll
            for (int k = 0; k < NBINS; k++) {
                float c = minv + range * ((float)k * inv31);
                float d = x - c;
                S += __expf(npre * d * d);
            }
        }
        __syncthreads();                      // rsa visible

        if (!isA) {
            float rsb = (idx < N) ? (1.0f / S) : 0.0f;
            float s = rsa_s[tn] * rsb;        // combined normalizer on B row
#pragma unroll
            for (int q = 0; q < 8; q++) {
                float4 v;
                float c, d;
                c = minv + range * ((float)(4 * q + 0) * inv31); d = x - c; v.x = __expf(npre * d * d) * s;
                c = minv + range * ((float)(4 * q + 1) * inv31); d = x - c; v.y = __expf(npre * d * d) * s;
                c = minv + range * ((float)(4 * q + 2) * inv31); d = x - c; v.z = __expf(npre * d * d) * s;
                c = minv + range * ((float)(4 * q + 3) * inv31); d = x - c; v.w = __expf(npre * d * d) * s;
                Wrow[q] = v;
            }
        }
        __syncthreads();

        // FMA phase: 8 element-pairs, 8x8 outer product per lane
#pragma unroll
        for (int it = 0; it < 8; it++) {
            const float4* Ar = Abase + (2 * it) * RQ;
            const float4* Br = Bbase + (2 * it) * RQ;
            float4 a0 = Ar[0];
            float4 a1 = Ar[1];
            float4 b0 = Br[0];
            float4 b1 = Br[1];
            ull ap[4];
            ap[0] = *(const ull*)&a0.x;   // {k0,k1}
            ap[1] = *(const ull*)&a0.z;   // {k2,k3}
            ap[2] = *(const ull*)&a1.x;   // {k4,k5}
            ap[3] = *(const ull*)&a1.z;   // {k6,k7}
            ull bb[8];
            bb[0] = dup_f32(b0.x); bb[1] = dup_f32(b0.y);
            bb[2] = dup_f32(b0.z); bb[3] = dup_f32(b0.w);
            bb[4] = dup_f32(b1.x); bb[5] = dup_f32(b1.y);
            bb[6] = dup_f32(b1.z); bb[7] = dup_f32(b1.w);
#pragma unroll
            for (int r = 0; r < 4; r++)
#pragma unroll
                for (int c = 0; c < 8; c++)
                    ffma2(acc2[r][c], ap[r], bb[c]);
        }
    }

    // epilogue: combine pair-halves via shuffle (commutative add -> identical
    // in both lanes), then the 8 warps' partials via smem (reuse SH)
    __syncthreads();
    float* sred = (float*)SH;
#pragma unroll
    for (int r = 0; r < 4; r++)
#pragma unroll
        for (int c = 0; c < 8; c++) {
            unsigned lo32, hi32;
            asm("mov.b64 {%0, %1}, %2;" : "=r"(lo32), "=r"(hi32) : "l"(acc2[r][c]));
            float flo = __uint_as_float(lo32);
            float fhi = __uint_as_float(hi32);
            flo += __shfl_xor_sync(0xFFFFFFFFu, flo, 16);
            fhi += __shfl_xor_sync(0xFFFFFFFFu, fhi, 16);
            if (half == 0) {
                int k0 = kp * 8 + 2 * r;
                int l  = lp * 8 + c;
                sred[warp * 1024 + (k0    ) * NBINS + l] = flo;
                sred[warp * 1024 + (k0 + 1) * NBINS + l] = fhi;
            }
        }
    __syncthreads();
    // [cell][block] layout: contiguous per-cell rows for the reduce kernel
    for (int cell = t; cell < NCELL; cell += NT) {
        float s = 0.0f;
#pragma unroll
        for (int w = 0; w < 8; w++) s += sred[w * 1024 + cell];
        g_part[cell * GBLK + blockIdx.x] = s;
    }
}

// Deterministic fp64 second-stage reduction: one BLOCK per cell (1024 blocks),
// 128 threads, coalesced contiguous loads, fixed-order pairwise tree.
__global__ void mi_reduce() {
    __shared__ double sd[128];
    int cell = blockIdx.x;
    int t = threadIdx.x;
    const float* p = g_part + cell * GBLK;
    double s = 0.0;
    s += (double)p[t];                          // GBLK=296 > 128
    s += (double)p[t + 128];
    if (t + 256 < GBLK) s += (double)p[t + 256];
    sd[t] = s;
    __syncthreads();
#pragma unroll
    for (int o = 64; o > 0; o >>= 1) {
        if (t < o) sd[t] = sd[t] + sd[t + o];   // fixed tree order -> deterministic
        __syncthreads();
    }
    if (t == 0) g_pab[cell] = sd[0];
}

// epilogue: pa/pb as row/col sums, MI in fp64, write -mi
__global__ void mi_final(float* __restrict__ out, int N) {
    __shared__ double pa[NBINS], pb[NBINS], red[32];
    int t = threadIdx.x;
    double invN = 1.0 / (double)N;
    if (t < 32) {
        double s = 0.0;
        for (int l = 0; l < NBINS; l++) s += g_pab[t * NBINS + l];
        pa[t] = s * invN;
    } else if (t < 64) {
        int l = t - 32;
        double s = 0.0;
        for (int k = 0; k < NBINS; k++) s += g_pab[k * NBINS + l];
        pb[l] = s * invN;
    }
    __syncthreads();

    int k = t >> 5, l = t & 31;                 // t in [0,1024): one cell per thread
    double pab  = g_pab[t] * invN;
    double papb = pa[k] * pb[l];
    double term = pab * log((pab + 1e-7) / (papb + 1e-7) + 1e-7);

#pragma unroll
    for (int o = 16; o > 0; o >>= 1)
        term += __shfl_xor_sync(0xFFFFFFFFu, term, o);
    if (l == 0) red[k] = term;                  // k == warp id (32 warps)
    __syncthreads();
    if (t < 32) {
        double v = red[t];
#pragma unroll
        for (int o = 16; o > 0; o >>= 1)
            v += __shfl_xor_sync(0xFFFFFFFFu, v, o);
        if (t == 0) *out = (float)(-v);
    }
}

extern "C" void kernel_launch(void* const* d_in, const int* in_sizes, int n_in,
                              void* d_out, int out_size) {
    const float* pred = (const float*)d_in[0];
    const float* tgt  = (const float*)d_in[1];
    int N = in_sizes[0];
    int numTiles = (N + TILE - 1) / TILE;

    mi_init<<<1, 1>>>();
    mi_minmax<<<1184, 256>>>(pred, tgt, N);
    mi_main<<<GBLK, NT>>>(pred, tgt, N, numTiles);
    mi_reduce<<<NCELL, 128>>>();
    mi_final<<<1, 1024>>>((float*)d_out, N);
}

// round 9
// speedup vs baseline: 1.0946x; 1.0946x over previous
#include <cuda_runtime.h>
#include <cuda_bf16.h>
#include <math.h>

#define NBINS 32
#define TILE  128
#define NT    256
#define GBLK  444          // 148 SMs * 3 resident blocks
#define RQ    9            // smem row stride in float4 (8 data quads + 1 pad)
#define NCELL (NBINS * NBINS)
#define BUFQ  (2 * TILE * RQ)                 // float4s per buffer (WA+WB)
#define SMEM_BYTES (2 * BUFQ * (int)sizeof(float4))   // 73,728 B (double buffer)

// ---------------- scratch (no allocations allowed) ----------------
__device__ unsigned g_minbits;
__device__ unsigned g_maxbits;
__device__ float    g_part[NCELL * GBLK];   // [cell][block] fp32 partials (~1.8 MB)
__device__ double   g_pab[NCELL];           // fp64 joint histogram sums

// order-preserving encoding so uint atomicMin/Max give exact float min/max
__device__ __forceinline__ unsigned enc_f(float v) {
    unsigned u = __float_as_uint(v);
    return (u & 0x80000000u) ? ~u : (u | 0x80000000u);
}
__device__ __forceinline__ float dec_f(unsigned u) {
    return (u & 0x80000000u) ? __uint_as_float(u & 0x7FFFFFFFu)
                             : __uint_as_float(~u);
}

// packed fp32x2 FMA: each half is an exact IEEE fp32 FMA (bit-identical to fmaf)
__device__ __forceinline__ void ffma2(unsigned long long& d,
                                      unsigned long long a,
                                      unsigned long long b) {
    asm("fma.rn.f32x2 %0, %1, %2, %0;" : "+l"(d) : "l"(a), "l"(b));
}
__device__ __forceinline__ unsigned long long dup_f32(float v) {
    unsigned long long r;
    asm("mov.b64 %0, {%1, %1};" : "=l"(r) : "r"(__float_as_uint(v)));
    return r;
}

__global__ void mi_init() {
    g_minbits = 0xFFFFFFFFu;
    g_maxbits = 0u;
}

// no-op probe: shifts mi_main to global launch index 5 so ncu (-s 5 -c 1)
// captures the hot kernel instead of mi_reduce.
__global__ void mi_probe() {}

__global__ void mi_minmax(const float* __restrict__ p,
                          const float* __restrict__ t, int N) {
    unsigned lmin = 0xFFFFFFFFu, lmax = 0u;
    int stride = gridDim.x * blockDim.x;
    int gtid = blockIdx.x * blockDim.x + threadIdx.x;
    int n4 = N >> 2;
    const float4* p4 = (const float4*)p;
    const float4* t4 = (const float4*)t;
    for (int i = gtid; i < n4; i += stride) {
        float4 a = __ldg(p4 + i);
        float4 b = __ldg(t4 + i);
        unsigned u;
        u = enc_f(a.x); lmin = min(lmin, u); lmax = max(lmax, u);
        u = enc_f(a.y); lmin = min(lmin, u); lmax = max(lmax, u);
        u = enc_f(a.z); lmin = min(lmin, u); lmax = max(lmax, u);
        u = enc_f(a.w); lmin = min(lmin, u); lmax = max(lmax, u);
        u = enc_f(b.x); lmin = min(lmin, u); lmax = max(lmax, u);
        u = enc_f(b.y); lmin = min(lmin, u); lmax = max(lmax, u);
        u = enc_f(b.z); lmin = min(lmin, u); lmax = max(lmax, u);
        u = enc_f(b.w); lmin = min(lmin, u); lmax = max(lmax, u);
    }
    for (int i = (n4 << 2) + gtid; i < N; i += stride) {   // tail
        unsigned u = enc_f(__ldg(p + i));
        lmin = min(lmin, u); lmax = max(lmax, u);
        u = enc_f(__ldg(t + i));
        lmin = min(lmin, u); lmax = max(lmax, u);
    }
#pragma unroll
    for (int o = 16; o > 0; o >>= 1) {
        lmin = min(lmin, __shfl_xor_sync(0xFFFFFFFFu, lmin, o));
        lmax = max(lmax, __shfl_xor_sync(0xFFFFFFFFu, lmax, o));
    }
    __shared__ unsigned smin[8], smax[8];
    int wid = threadIdx.x >> 5;
    if ((threadIdx.x & 31) == 0) { smin[wid] = lmin; smax[wid] = lmax; }
    __syncthreads();
    if (threadIdx.x == 0) {
        unsigned m = smin[0], M = smax[0];
        int nw = blockDim.x >> 5;
        for (int w = 1; w < nw; w++) { m = min(m, smin[w]); M = max(M, smax[w]); }
        atomicMin(&g_minbits, m);   // exact, order-independent -> deterministic
        atomicMax(&g_maxbits, M);
    }
}

// Main kernel: EXACT R7 per-thread arithmetic (validated, rel_err 1.43e-5).
// Double-buffered smem tiles -> ONE barrier per tile: with two buffers,
// writes of tile t+1 conflict only with reads of tile t-1, which the W->F
// sync of tile t already orders. Weight phase of next tile overlaps FMA
// phase of slower warps.
__global__ __launch_bounds__(NT, 3)
void mi_main(const float* __restrict__ pred, const float* __restrict__ tgt,
             int N, int numTiles) {
    extern __shared__ float4 SH[];   // 2 buffers x (WA + WB)

    float minv = dec_f(g_minbits);
    float maxv = dec_f(g_maxbits);
    if (maxv <= 1.0f && minv >= 0.0f) { minv = 0.0f; maxv = 1.0f; }
    float range  = maxv - minv;
    const float inv31 = 1.0f / 31.0f;
    float sigma  = range / 31.0f;                 // /(NUM_BINS-1) * SIGMA_RATIO(=1)
    float preterm = 1.0f / ((2.0f * sigma) * sigma);
    float npre   = 0.0f - preterm;

    int t  = threadIdx.x;
    int tn = t & (TILE - 1);
    const float* src = (t < TILE) ? pred : tgt;   // threads 0..127: wa rows, 128..255: wb rows
    int woff = (t < TILE) ? 0 : TILE * RQ;

    // outer-product roles
    int warp = t >> 5;            // n-subgroup: elements [warp*16, warp*16+16)
    int lane = t & 31;
    int kp   = lane >> 3;         // k-block: rows kp*8 .. kp*8+7
    int lp   = lane & 7;          // l-block: cols lp*4 .. lp*4+3

    // packed accumulators: acc2[rp][c] holds cells k = kp*8 + 2*rp + {0,1}, l = lp*4 + c
    unsigned long long acc2[4][4];
#pragma unroll
    for (int rp = 0; rp < 4; rp++)
#pragma unroll
        for (int c = 0; c < 4; c++) acc2[rp][c] = 0ull;

    int ibuf = 0;
    for (int tile = blockIdx.x; tile < numTiles; tile += gridDim.x, ibuf ^= 1) {
        float4* BUF  = SH + ibuf * BUFQ;
        float4* Wrow = BUF + woff + tn * RQ;

        int idx = tile * TILE + tn;
        float x = (idx < N) ? __ldg(src + idx) : 0.0f;

        // pass 1: compute each exp ONCE (k ascending, same S add order),
        // store unnormalized to smem, accumulate S
        float S = 0.0f;
#pragma unroll
        for (int q = 0; q < 8; q++) {
            float4 v;
            float c, d;
            c = minv + range * ((float)(4 * q + 0) * inv31); d = x - c; v.x = __expf(npre * d * d);
            c = minv + range * ((float)(4 * q + 1) * inv31); d = x - c; v.y = __expf(npre * d * d);
            c = minv + range * ((float)(4 * q + 2) * inv31); d = x - c; v.z = __expf(npre * d * d);
            c = minv + range * ((float)(4 * q + 3) * inv31); d = x - c; v.w = __expf(npre * d * d);
            S += v.x; S += v.y; S += v.z; S += v.w;
            Wrow[q] = v;
        }
        float rsc = (idx < N) ? (1.0f / S) : 0.0f;

        // pass 2: in-place scale by rsc (same multiply as R7, no recompute)
#pragma unroll
        for (int q = 0; q < 8; q++) {
            float4 v = Wrow[q];
            v.x *= rsc; v.y *= rsc; v.z *= rsc; v.w *= rsc;
            Wrow[q] = v;
        }
        __syncthreads();    // the ONLY barrier per tile: W(t) -> F(t)

        // FMA phase: 16 elements, 8x4 outer product each, as 16 fp32x2 FMAs
        const float4* Arow0 = BUF + (warp * 16) * RQ + 2 * kp;
        const float4* Brow0 = BUF + TILE * RQ + (warp * 16) * RQ + lp;
#pragma unroll 4
        for (int e = 0; e < 16; e++) {
            float4 a0 = Arow0[e * RQ];
            float4 a1 = Arow0[e * RQ + 1];
            float4 b  = Brow0[e * RQ];
            unsigned long long ap[4];
            ap[0] = *(const unsigned long long*)&a0.x;   // {k0,k1}
            ap[1] = *(const unsigned long long*)&a0.z;   // {k2,k3}
            ap[2] = *(const unsigned long long*)&a1.x;   // {k4,k5}
            ap[3] = *(const unsigned long long*)&a1.z;   // {k6,k7}
            unsigned long long bb[4];
            bb[0] = dup_f32(b.x);
            bb[1] = dup_f32(b.y);
            bb[2] = dup_f32(b.z);
            bb[3] = dup_f32(b.w);
#pragma unroll
            for (int rp = 0; rp < 4; rp++)
#pragma unroll
                for (int c = 0; c < 4; c++)
                    ffma2(acc2[rp][c], ap[rp], bb[c]);
        }
    }

    // combine the 8 warps' accumulators (reuse SH as float[8][1024])
    __syncthreads();
    float* sred = (float*)SH;
#pragma unroll
    for (int rp = 0; rp < 4; rp++)
#pragma unroll
        for (int c = 0; c < 4; c++) {
            unsigned lo32, hi32;
            asm("mov.b64 {%0, %1}, %2;" : "=r"(lo32), "=r"(hi32) : "l"(acc2[rp][c]));
            int k0 = kp * 8 + 2 * rp;
            int l  = lp * 4 + c;
            sred[warp * 1024 + (k0    ) * NBINS + l] = __uint_as_float(lo32);
            sred[warp * 1024 + (k0 + 1) * NBINS + l] = __uint_as_float(hi32);
        }
    __syncthreads();
    // [cell][block] layout: contiguous per-cell rows for the reduce kernel
    for (int cell = t; cell < NCELL; cell += NT) {
        float s = 0.0f;
#pragma unroll
        for (int w = 0; w < 8; w++) s += sred[w * 1024 + cell];
        g_part[cell * GBLK + blockIdx.x] = s;
    }
}

// Deterministic fp64 second-stage reduction: one BLOCK per cell (1024 blocks),
// 128 threads, coalesced contiguous loads, fixed-order pairwise tree.
__global__ void mi_reduce() {
    __shared__ double sd[128];
    int cell = blockIdx.x;
    int t = threadIdx.x;
    const float* p = g_part + cell * GBLK;
    double s = 0.0;
    s += (double)p[t];                          // GBLK=444 > 128: t always valid
    s += (double)p[t + 128];
    s += (double)p[t + 256];
    if (t + 384 < GBLK) s += (double)p[t + 384];
    sd[t] = s;
    __syncthreads();
#pragma unroll
    for (int o = 64; o > 0; o >>= 1) {
        if (t < o) sd[t] = sd[t] + sd[t + o];   // fixed tree order -> deterministic
        __syncthreads();
    }
    if (t == 0) g_pab[cell] = sd[0];
}

// epilogue: pa/pb as row/col sums, MI in fp64, write -mi
__global__ void mi_final(float* __restrict__ out, int N) {
    __shared__ double pa[NBINS], pb[NBINS], red[32];
    int t = threadIdx.x;
    double invN = 1.0 / (double)N;
    if (t < 32) {
        double s = 0.0;
        for (int l = 0; l < NBINS; l++) s += g_pab[t * NBINS + l];
        pa[t] = s * invN;
    } else if (t < 64) {
        int l = t - 32;
        double s = 0.0;
        for (int k = 0; k < NBINS; k++) s += g_pab[k * NBINS + l];
        pb[l] = s * invN;
    }
    __syncthreads();

    int k = t >> 5, l = t & 31;                 // t in [0,1024): one cell per thread
    double pab  = g_pab[t] * invN;
    double papb = pa[k] * pb[l];
    double term = pab * log((pab + 1e-7) / (papb + 1e-7) + 1e-7);

#pragma unroll
    for (int o = 16; o > 0; o >>= 1)
        term += __shfl_xor_sync(0xFFFFFFFFu, term, o);
    if (l == 0) red[k] = term;                  // k == warp id (32 warps)
    __syncthreads();
    if (t < 32) {
        double v = red[t];
#pragma unroll
        for (int o = 16; o > 0; o >>= 1)
            v += __shfl_xor_sync(0xFFFFFFFFu, v, o);
        if (t == 0) *out = (float)(-v);
    }
}

extern "C" void kernel_launch(void* const* d_in, const int* in_sizes, int n_in,
                              void* d_out, int out_size) {
    const float* pred = (const float*)d_in[0];
    const float* tgt  = (const float*)d_in[1];
    int N = in_sizes[0];
    int numTiles = (N + TILE - 1) / TILE;

    // allow >48KB dynamic smem (executes immediately; not a graph node)
    cudaFuncSetAttribute(mi_main, cudaFuncAttributeMaxDynamicSharedMemorySize,
                         SMEM_BYTES);

    mi_init<<<1, 1>>>();
    mi_minmax<<<1184, 256>>>(pred, tgt, N);
    mi_probe<<<1, 1>>>();   // shifts mi_main to ncu capture slot (launch idx 5)
    mi_main<<<GBLK, NT, SMEM_BYTES>>>(pred, tgt, N, numTiles);
    mi_reduce<<<NCELL, 128>>>();
    mi_final<<<1, 1024>>>((float*)d_out, N);
}